// round 4
// baseline (speedup 1.0000x reference)
#include <cuda_runtime.h>
#include <cuda_bf16.h>

// SNN dense (TTFS) — B=64, IN=1024 (+1 bias row), OUT=1024.
//   K1: stable rank-counting sort; emits packed {spike time, W byte offset}.
//   K2: chunk-parallel scan, 16 warps split k; 4 neurons/thread (float4 W).

#define BATCH 64
#define IN_SZ 1024
#define KTOT 1025          // IN_SZ + bias
#define OUT_SZ 1024
#define MAXT 100000.0f
#define EPSV 1e-10f
#define BIASV 1.0f

#define NW 16              // warps (K-chunks) per CTA
#define CHUNK ((KTOT + NW - 1) / NW)   // 65
#define MBLK 128           // outputs per CTA (4 per lane)

// Scratch: packed sorted stream per batch row. p.x = float bits of spike
// time, p.y = byte offset of that input's W row (idx * OUT_SZ * 4).
__device__ int2 g_pack[BATCH][KTOT + 1];

// ---------------------------------------------------------------------------
// Kernel 1: stable counting sort. grid = (9, 64), block = 128.
// ---------------------------------------------------------------------------
__global__ void __launch_bounds__(128) snn_sort_kernel(const float* __restrict__ X) {
    const int b = blockIdx.y;
    __shared__ float sx[KTOT + 3];

    for (int j = threadIdx.x; j < KTOT; j += blockDim.x)
        sx[j] = (j < IN_SZ) ? X[b * IN_SZ + j] : BIASV;
    if (threadIdx.x < 3) sx[KTOT + threadIdx.x] = 3.0e38f;  // pad for float4 reads
    __syncthreads();

    const int i = blockIdx.x * blockDim.x + threadIdx.x;
    if (blockIdx.x == 0 && threadIdx.x == 0) {
        int2 s; s.x = __float_as_int(MAXT); s.y = 0;
        g_pack[b][KTOT] = s;                 // next_x sentinel
    }
    if (i >= KTOT) return;

    const float xi = sx[i];
    int r = 0;
    const float4* sx4 = reinterpret_cast<const float4*>(sx);
    #pragma unroll 4
    for (int j4 = 0; j4 < (KTOT + 3) / 4; ++j4) {
        float4 v = sx4[j4];
        int j = j4 * 4;
        r += (v.x < xi) || (v.x == xi && (j + 0) < i);
        r += (v.y < xi) || (v.y == xi && (j + 1) < i);
        r += (v.z < xi) || (v.z == xi && (j + 2) < i);
        r += (v.w < xi) || (v.w == xi && (j + 3) < i);
    }
    int2 p; p.x = __float_as_int(xi); p.y = i * (OUT_SZ * 4);
    g_pack[b][r] = p;
}

// ---------------------------------------------------------------------------
// Kernel 2: chunk-parallel scan. grid = (OUT_SZ/MBLK, BATCH) = (8, 64),
// block = 512. Warp w owns k in [w*CHUNK, ...); lane L owns 4 outputs
// m = mbase + 4L .. 4L+3 (one LDG.128 per k).
// ---------------------------------------------------------------------------
__global__ void __launch_bounds__(512) snn_scan_kernel(const float* __restrict__ W,
                                                       float* __restrict__ out) {
    const int b = blockIdx.y;
    const int mbase = blockIdx.x * MBLK;

    __shared__ int2   sp[KTOT + 1];       // packed {x, byteoff}
    __shared__ float4 pw4[NW][MBLK / 4];  // chunk sums of w
    __shared__ float4 pt4[NW][MBLK / 4];  // chunk sums of w*x
    __shared__ float4 pm4[NW][MBLK / 4];  // per-chunk minima

    for (int j = threadIdx.x; j < KTOT + 1; j += blockDim.x)
        sp[j] = g_pack[b][j];
    __syncthreads();

    const int w    = threadIdx.x >> 5;
    const int lane = threadIdx.x & 31;
    const char* Wb = (const char*)W + (size_t)(mbase + 4 * lane) * 4;

    const int k0 = w * CHUNK;
    const int k1 = (k0 + CHUNK < KTOT) ? (k0 + CHUNK) : KTOT;

    // ---- pass 1: chunk partial sums ----
    float4 s = make_float4(0.f, 0.f, 0.f, 0.f);
    float4 t = make_float4(0.f, 0.f, 0.f, 0.f);
    #pragma unroll 4
    for (int k = k0; k < k1; ++k) {
        const int2 p = sp[k];
        const float x = __int_as_float(p.x);
        const float4 wv = *reinterpret_cast<const float4*>(Wb + p.y);
        s.x += wv.x; t.x += wv.x * x;
        s.y += wv.y; t.y += wv.y * x;
        s.z += wv.z; t.z += wv.z * x;
        s.w += wv.w; t.w += wv.w * x;
    }
    pw4[w][lane] = s;
    pt4[w][lane] = t;
    __syncthreads();

    // ---- exclusive prefix over earlier chunks ----
    float4 cw = make_float4(0.f, 0.f, 0.f, 0.f);
    float4 ct = make_float4(0.f, 0.f, 0.f, 0.f);
    for (int c = 0; c < w; ++c) {
        float4 a = pw4[c][lane], d = pt4[c][lane];
        cw.x += a.x; cw.y += a.y; cw.z += a.z; cw.w += a.w;
        ct.x += d.x; ct.y += d.y; ct.z += d.z; ct.w += d.w;
    }

    // ---- pass 2: scan chunk, evaluate candidates ----
    float4 best = make_float4(MAXT, MAXT, MAXT, MAXT);
    int2 pc = sp[k0];
    #pragma unroll 4
    for (int k = k0; k < k1; ++k) {
        const float x = __int_as_float(pc.x);
        const int  off = pc.y;
        pc = sp[k + 1];
        const float nx = __int_as_float(pc.x);
        const float4 wv = *reinterpret_cast<const float4*>(Wb + off);

        // den = cw-1; den<0 <=> cw<1 (exact: Sterbenz on [0.5,2], sign exact
        // elsewhere). Upper clip dropped: |cw| <= sum|w| ~ 99 << 1e5.
        {
            cw.x += wv.x; ct.x += wv.x * x;
            float den  = cw.x - 1.0f;
            float cand = __fdividef(ct.x, fmaxf(den, EPSV));
            bool bad = (den < 0.f) | (cand < x) | (cand > nx);
            best.x = fminf(best.x, bad ? MAXT : cand);
        }
        {
            cw.y += wv.y; ct.y += wv.y * x;
            float den  = cw.y - 1.0f;
            float cand = __fdividef(ct.y, fmaxf(den, EPSV));
            bool bad = (den < 0.f) | (cand < x) | (cand > nx);
            best.y = fminf(best.y, bad ? MAXT : cand);
        }
        {
            cw.z += wv.z; ct.z += wv.z * x;
            float den  = cw.z - 1.0f;
            float cand = __fdividef(ct.z, fmaxf(den, EPSV));
            bool bad = (den < 0.f) | (cand < x) | (cand > nx);
            best.z = fminf(best.z, bad ? MAXT : cand);
        }
        {
            cw.w += wv.w; ct.w += wv.w * x;
            float den  = cw.w - 1.0f;
            float cand = __fdividef(ct.w, fmaxf(den, EPSV));
            bool bad = (den < 0.f) | (cand < x) | (cand > nx);
            best.w = fminf(best.w, bad ? MAXT : cand);
        }
    }
    pm4[w][lane] = best;
    __syncthreads();

    // ---- final min across chunks: threads 0..127, one output each ----
    if (threadIdx.x < MBLK) {
        const float* pmf = reinterpret_cast<const float*>(pm4);
        float bb = MAXT;
        #pragma unroll
        for (int c = 0; c < NW; ++c)
            bb = fminf(bb, pmf[c * MBLK + threadIdx.x]);
        out[b * OUT_SZ + mbase + threadIdx.x] = bb;
    }
}

// ---------------------------------------------------------------------------
extern "C" void kernel_launch(void* const* d_in, const int* in_sizes, int n_in,
                              void* d_out, int out_size) {
    const float* X = (const float*)d_in[0];
    const float* W = (const float*)d_in[1];
    if (n_in >= 2 && in_sizes[0] != BATCH * IN_SZ && in_sizes[1] == BATCH * IN_SZ) {
        X = (const float*)d_in[1];
        W = (const float*)d_in[0];
    }
    float* out = (float*)d_out;

    dim3 gs((KTOT + 127) / 128, BATCH);       // (9, 64)
    snn_sort_kernel<<<gs, 128>>>(X);

    dim3 gm(OUT_SZ / MBLK, BATCH);            // (8, 64)
    snn_scan_kernel<<<gm, 512>>>(W, out);
}

// round 8
// speedup vs baseline: 1.1212x; 1.1212x over previous
#include <cuda_runtime.h>
#include <cuda_bf16.h>

// SNN dense (TTFS) — B=64, IN=1024 (+1 bias row), OUT=1024.
//   K1: stable rank-count sort with packed 64-bit keys; emits {x, W byteoff}.
//   K2: persistent work-stealing scan; 16 warps split k per item,
//       2 neurons/lane (MBLK=64), threshold folded into accumulator.

#define BATCH 64
#define IN_SZ 1024
#define KTOT 1025          // IN_SZ + bias
#define OUT_SZ 1024
#define MAXT 100000.0f
#define EPSV 1e-10f
#define BIASV 1.0f

#define NW 16              // warps (K-chunks) per item
#define CHUNK ((KTOT + NW - 1) / NW)   // 65
#define MBLK 64            // outputs per item (2 per lane)
#define NITEMS (BATCH * (OUT_SZ / MBLK))   // 1024
#define GRID_SCAN 592      // 148 SMs x 4 CTAs

// Scratch (device globals; no allocation allowed)
__device__ int2 g_pack[BATCH][KTOT + 1];  // {float bits of x, W byte offset}
__device__ unsigned g_ticket;

// ---------------------------------------------------------------------------
// Kernel 1: stable counting sort via packed u64 keys. grid = (9, 64), blk 128.
// key = (float_bits << 32) | index : positive floats order as uints, index
// tie-break = exact jnp.argsort stability.
// ---------------------------------------------------------------------------
__global__ void __launch_bounds__(128) snn_sort_kernel(const float* __restrict__ X) {
    const int b = blockIdx.y;
    __shared__ unsigned long long sk[KTOT + 1];  // +1 pad for ull2 reads

    for (int j = threadIdx.x; j < KTOT; j += blockDim.x) {
        float v = (j < IN_SZ) ? X[b * IN_SZ + j] : BIASV;
        sk[j] = ((unsigned long long)__float_as_uint(v) << 32) | (unsigned)j;
    }
    if (threadIdx.x == 0) {
        sk[KTOT] = ~0ull;                      // pad: never smaller
        if (blockIdx.x == 0 && b == 0) g_ticket = 0;   // reset work queue
        int2 s; s.x = __float_as_int(MAXT); s.y = 0;
        if (blockIdx.x == 0) g_pack[b][KTOT] = s;      // next_x sentinel
    }
    __syncthreads();

    const int i = blockIdx.x * blockDim.x + threadIdx.x;
    if (i >= KTOT) return;

    const unsigned long long ki = sk[i];
    int r = 0;
    const ulonglong2* sk2 = reinterpret_cast<const ulonglong2*>(sk);
    #pragma unroll 4
    for (int j2 = 0; j2 < (KTOT + 1) / 2; ++j2) {
        ulonglong2 v = sk2[j2];
        r += (v.x < ki);
        r += (v.y < ki);
    }
    int2 p;
    p.x = (int)(ki >> 32);                     // float bits of x
    p.y = ((int)(ki & 0xFFFFFFFFu)) * (OUT_SZ * 4);  // W row byte offset
    g_pack[b][r] = p;
}

// ---------------------------------------------------------------------------
// Kernel 2: persistent work-stealing scan. grid = 592, block = 512.
// Item = (b, m-block of 64). Warp w owns k in [w*CHUNK, ...); lane L owns
// outputs mbase + 2L, 2L+1. Accumulator cw starts at -1 (threshold folded).
// ---------------------------------------------------------------------------
__global__ void __launch_bounds__(512, 4) snn_scan_kernel(const float* __restrict__ W,
                                                          float* __restrict__ out) {
    __shared__ int2  sp[KTOT + 1];
    __shared__ float pw[NW][MBLK];
    __shared__ float pt[NW][MBLK];
    __shared__ float pm[NW][MBLK];
    __shared__ unsigned s_item;

    const int w    = threadIdx.x >> 5;
    const int lane = threadIdx.x & 31;
    const int k0 = w * CHUNK;
    const int k1 = (k0 + CHUNK < KTOT) ? (k0 + CHUNK) : KTOT;

    for (;;) {
        if (threadIdx.x == 0) s_item = atomicAdd(&g_ticket, 1u);
        __syncthreads();
        const unsigned item = s_item;
        if (item >= NITEMS) return;

        const int b     = item >> 4;            // item / (OUT_SZ/MBLK)
        const int mbase = (item & 15) * MBLK;

        for (int j = threadIdx.x; j < KTOT + 1; j += blockDim.x)
            sp[j] = g_pack[b][j];
        __syncthreads();

        const char* Wb = (const char*)W + (size_t)(mbase + 2 * lane) * 4;

        // ---- pass 1: chunk partial sums ----
        float s0 = 0.f, t0 = 0.f, s1 = 0.f, t1 = 0.f;
        #pragma unroll 4
        for (int k = k0; k < k1; ++k) {
            const int2 p = sp[k];
            const float x = __int_as_float(p.x);
            const float2 wv = *reinterpret_cast<const float2*>(Wb + p.y);
            s0 += wv.x; t0 = fmaf(wv.x, x, t0);
            s1 += wv.y; t1 = fmaf(wv.y, x, t1);
        }
        pw[w][2 * lane] = s0;     pt[w][2 * lane] = t0;
        pw[w][2 * lane + 1] = s1; pt[w][2 * lane + 1] = t1;
        __syncthreads();

        // ---- exclusive prefix (threshold folded: start at -1) ----
        float cw0 = -1.f, ct0 = 0.f, cw1 = -1.f, ct1 = 0.f;
        for (int c = 0; c < w; ++c) {
            cw0 += pw[c][2 * lane];     ct0 += pt[c][2 * lane];
            cw1 += pw[c][2 * lane + 1]; ct1 += pt[c][2 * lane + 1];
        }

        // ---- pass 2: scan chunk, evaluate candidates ----
        float best0 = MAXT, best1 = MAXT;
        int2 pc = sp[k0];
        #pragma unroll 4
        for (int k = k0; k < k1; ++k) {
            const float x = __int_as_float(pc.x);
            const int off = pc.y;
            pc = sp[k + 1];
            const float nx = __int_as_float(pc.x);
            const float2 wv = *reinterpret_cast<const float2*>(Wb + off);

            cw0 += wv.x; ct0 = fmaf(wv.x, x, ct0);
            {
                float den  = fmaxf(cw0, EPSV);            // cw<0 => den=EPS
                float cand = __fdividef(ct0, den);
                bool bad = (cw0 < 0.f) | (cand < x) | (cand > nx);
                if (!bad) best0 = fminf(best0, cand);
            }
            cw1 += wv.y; ct1 = fmaf(wv.y, x, ct1);
            {
                float den  = fmaxf(cw1, EPSV);
                float cand = __fdividef(ct1, den);
                bool bad = (cw1 < 0.f) | (cand < x) | (cand > nx);
                if (!bad) best1 = fminf(best1, cand);
            }
        }
        pm[w][2 * lane]     = best0;
        pm[w][2 * lane + 1] = best1;
        __syncthreads();

        // ---- final min across chunks ----
        if (threadIdx.x < MBLK) {
            float bb = MAXT;
            #pragma unroll
            for (int c = 0; c < NW; ++c)
                bb = fminf(bb, pm[c][threadIdx.x]);
            out[b * OUT_SZ + mbase + threadIdx.x] = bb;
        }
        __syncthreads();   // protect sp/pm/s_item before next item
    }
}

// ---------------------------------------------------------------------------
extern "C" void kernel_launch(void* const* d_in, const int* in_sizes, int n_in,
                              void* d_out, int out_size) {
    const float* X = (const float*)d_in[0];
    const float* W = (const float*)d_in[1];
    if (n_in >= 2 && in_sizes[0] != BATCH * IN_SZ && in_sizes[1] == BATCH * IN_SZ) {
        X = (const float*)d_in[1];
        W = (const float*)d_in[0];
    }
    float* out = (float*)d_out;

    dim3 gs((KTOT + 127) / 128, BATCH);       // (9, 64)
    snn_sort_kernel<<<gs, 128>>>(X);

    snn_scan_kernel<<<GRID_SCAN, 512>>>(W, out);
}